// round 5
// baseline (speedup 1.0000x reference)
#include <cuda_runtime.h>

// Problem constants
#define NB    512       // batch B
#define NMF   256       // M features
#define INDIM 50
#define SROW  51        // padded S row (conflict-free smem, odd stride)
#define OFF_U 512
#define OFF_S 25088     // 512 + 512*48
#define OFF_W 37888     // OFF_S + 256*50
#define G     2         // batch elements per fwd block
#define NBLK  (NB/G)    // 256 fwd blocks

// Scratch (m-major rows, b contiguous -> coalesced reduction reads)
__device__ float g_ET [NMF*NB];
__device__ float g_EtT[NMF*NB];
__device__ float g_ExT[NMF*NB];
__device__ float g_GwT[512*NB];
__device__ float g_UvT[48*NB];

__device__ __forceinline__ float warp_sum(float v) {
#pragma unroll
    for (int o = 16; o; o >>= 1) v += __shfl_down_sync(0xffffffffu, v, o);
    return v;
}
__device__ __forceinline__ float xor_sum(float v) {
#pragma unroll
    for (int o = 16; o; o >>= 1) v += __shfl_xor_sync(0xffffffffu, v, o);
    return v;
}

// smem floats: S[256*51] | inp[2*64] | esm[2*256] | red[4 stages * 32]
#define SMEM_FLOATS (NMF*SROW + G*64 + G*256 + 128)

// 512 threads: g = t>>8 (one batch element per thread), m = t&255.
__global__ __launch_bounds__(512, 2) void fwd_kernel(
    const float* __restrict__ U0, const float* __restrict__ U1,
    const float* __restrict__ U2, const float* __restrict__ S,
    const float* __restrict__ w,  const float* __restrict__ tn,
    const float* __restrict__ obs, const int* __restrict__ idx,
    float* __restrict__ out)
{
    extern __shared__ float sm[];
    float* Ssm = sm;                 // 256*51
    float* inp = Ssm + NMF*SROW;     // 2*64
    float* esm = inp + G*64;         // 2*256
    float* red = esm + G*256;        // [stage][g*8 + w8] fp, [stage][16 + g*8 + w8] jp

    const int b0   = blockIdx.x * G;
    const int t    = threadIdx.x;
    const int lane = t & 31;
    const int wid  = t >> 5;         // 0..15
    const int m    = t & 255;
    const int g    = t >> 8;         // 0 or 1  (== wid>>3)
    const int w8   = wid & 7;

    // Load S via float4, scatter into padded smem rows
    {
        const float4* S4 = (const float4*)S;
        for (int i = t; i < (NMF*INDIM)/4; i += 512) {
            float4 v = S4[i];
            int base = i * 4;
#pragma unroll
            for (int c = 0; c < 4; c++) {
                int id = base + c;
                int mm = id / INDIM;
                int jj = id - mm*INDIM;
                float vc = (c == 0) ? v.x : (c == 1) ? v.y : (c == 2) ? v.z : v.w;
                Ssm[mm*SROW + jj] = vc;
            }
        }
    }
    // Gather Uvec (2 b x 48 values)
    if (t < G*48) {
        int gg = t / 48, j = t - gg*48;
        int v = j >> 4, r = j & 15;
        int iv = idx[(b0 + gg)*3 + v];
        const float* Uv = (v == 0) ? U0 : (v == 1) ? U1 : U2;
        inp[gg*64 + 2 + j] = Uv[iv*16 + r];
    }
    __syncthreads();

    const float wc = w[m], ws = w[256 + m];
    const float s0 = Ssm[m*SROW + 0], s1 = Ssm[m*SROW + 1];
    const float scaleT = tn[b0 + g];
    const float obs_g  = obs[b0 + g];
    const float* inpg  = inp + g*64;

    // beta = sum_r U0r*U1r*U2r : lanes 0..15 hold one term each, xor-reduce
    float bt = 0.f;
    if (lane < 16) bt = inpg[2 + lane] * inpg[18 + lane] * inpg[34 + lane];
    const float beta = xor_sum(bt);

    // phi constant part (Uvec columns never change across stages)
    float phiU = 0.f;
#pragma unroll
    for (int j = 2; j < INDIM; j++) phiU = fmaf(Ssm[m*SROW + j], inpg[j], phiU);

    // ---- RK4 stages (t = 0, 0.5, 0.5, 1 ; h = 1), state in registers ----
    float in0 = 0.f, in1 = beta;
    float cpS[4], spS[4], kS[4], JS[4], xS[4], tS[4];
#pragma unroll
    for (int i = 0; i < 4; i++) {
        xS[i] = in1; tS[i] = in0;
        float phi = phiU + s0*in0 + s1*in1;
        float cp, sp;
        sincosf(phi, &sp, &cp);
        cpS[i] = cp; spS[i] = sp;
        float fp = xor_sum(cp*wc + sp*ws);
        float jp = xor_sum((cp*ws - sp*wc) * s1);
        if (lane == 0) { red[i*32 + g*8 + w8] = fp; red[i*32 + 16 + g*8 + w8] = jp; }
        __syncthreads();
        float F = 0.f, JJ = 0.f;
#pragma unroll
        for (int q = 0; q < 8; q++) { F += red[i*32 + g*8 + q]; JJ += red[i*32 + 16 + g*8 + q]; }
        float k = scaleT * F;
        kS[i] = k; JS[i] = scaleT * JJ;
        if (i == 0 || i == 1)      { in1 = beta + 0.5f*k; in0 = scaleT * 0.5f; }
        else if (i == 2)           { in1 = beta + k;      in0 = scaleT; }
    }

    // Discrete-adjoint RK4 coefficients (every thread, registers)
    const float J1 = JS[0], J2 = JS[1], J3 = JS[2], J4 = JS[3];
    const float xT  = beta + (kS[0] + 2.f*kS[1] + 2.f*kS[2] + kS[3]) * (1.f/6.f);
    const float lam = (xT - obs_g) * (1.f/512.f);
    const float a1 = J1;
    const float a2 = J2*(1.f + 0.5f*a1);
    const float a3 = J3*(1.f + 0.5f*a2);
    const float a4 = J4*(1.f + a3);
    const float A  = 1.f + (a1 + 2.f*a2 + 2.f*a3 + a4) * (1.f/6.f);
    float ch[4];
    {
        const float ls = lam * scaleT;
        ch[0] = ls * (1.f + J2 + 0.5f*J3*J2 + 0.25f*J4*J3*J2) * (1.f/6.f);
        ch[1] = ls * (2.f + J3 + 0.5f*J4*J3) * (1.f/6.f);
        ch[2] = ls * (2.f + J4) * (1.f/6.f);
        ch[3] = ls * (1.f/6.f);
    }
    const float lamA = lam * A;
    if (m == 0) out[b0 + g] = lamA;     // grad wrt beta (diagonal)

    // ---- pass 2: per-(b,m) weighted stage sums (all from registers) ----
    float e = 0.f, et = 0.f, ex = 0.f, gc = 0.f, gs = 0.f;
#pragma unroll
    for (int i = 0; i < 4; i++) {
        float d  = cpS[i]*ws - spS[i]*wc;
        float cd = ch[i] * d;
        e  += cd;
        et += cd * tS[i];
        ex += cd * xS[i];
        gc += ch[i] * cpS[i];
        gs += ch[i] * spS[i];
    }
    const int b = b0 + g;
    g_ET [m*NB + b] = e;
    g_EtT[m*NB + b] = et;
    g_ExT[m*NB + b] = ex;
    g_GwT[m*NB + b]         = gc;
    g_GwT[(256 + m)*NB + b] = gs;
    esm[g*256 + m] = e;
    if (t < G*48) {
        int gg = t / 48, j = t - gg*48;
        g_UvT[j*NB + b0 + gg] = inp[gg*64 + 2 + j];
    }
    __syncthreads();

    // ---- per-b Uvec gradient: sum_m e_m * S[m, 2+j] + beta-chain term ----
    // warp's g == its own g; 8 warps per g, 6 j's per warp
    {
        const float* eg = esm + g*256;
        const int jb = w8 * 6;
#pragma unroll
        for (int q = 0; q < 6; q++) {
            int j = jb + q;
            float s = 0.f;
#pragma unroll
            for (int k = 0; k < 8; k++) {
                int mm = lane + 32*k;
                s += eg[mm] * Ssm[mm*SROW + 2 + j];
            }
            s = warp_sum(s);
            if (lane == 0) {
                int v = j >> 4, r = j & 15;
                float u0 = inpg[2 + r], u1 = inpg[18 + r], u2 = inpg[34 + r];
                float pe = (v == 0) ? u1*u2 : (v == 1) ? u0*u2 : u0*u1;
                out[OFF_U + (b0 + g)*48 + j] = s + lamA * pe;
            }
        }
    }
}

// Cross-batch reductions: grad_S (256x50) and grad_w (512).
// blocks 0..511  : (m, j-half). jh=0: j 0..23 ; jh=1: j 24..47 + Et + Ex
// blocks 512..543: grad_w, 16 rows each (one per warp)
__global__ __launch_bounds__(512) void red_kernel(float* __restrict__ out)
{
    const int t = threadIdx.x, lane = t & 31, wid = t >> 5;   // wid 0..15
    const int bid = blockIdx.x;
    __shared__ float Esm[NB];

    if (bid < 2*NMF) {
        const int m  = bid >> 1;
        const int jh = bid & 1;
        Esm[t] = g_ET[m*NB + t];
        __syncthreads();
        const float4* E4 = (const float4*)Esm;
        const int ntask = jh ? 26 : 24;
#pragma unroll
        for (int r = 0; r < 2; r++) {
            int task = wid + 16*r;
            if (task >= ntask) break;
            int j = jh*24 + task;
            float s = 0.f;
            if (j < 48) {
                const float4* Uv4 = (const float4*)(g_UvT + j*NB);
#pragma unroll
                for (int k = 0; k < 4; k++) {
                    float4 e = E4[lane + 32*k];
                    float4 u = Uv4[lane + 32*k];
                    s += e.x*u.x + e.y*u.y + e.z*u.z + e.w*u.w;
                }
                s = warp_sum(s);
                if (lane == 0) out[OFF_S + m*INDIM + 2 + j] = s;
            } else {
                const float4* P4 = (const float4*)((j == 48) ? (g_EtT + m*NB)
                                                             : (g_ExT + m*NB));
#pragma unroll
                for (int k = 0; k < 4; k++) {
                    float4 p = P4[lane + 32*k];
                    s += p.x + p.y + p.z + p.w;
                }
                s = warp_sum(s);
                if (lane == 0) out[OFF_S + m*INDIM + (j - 48)] = s;
            }
        }
    } else {
        const int row = (bid - 2*NMF)*16 + wid;   // 0..511
        const float4* P4 = (const float4*)(g_GwT + row*NB);
        float s = 0.f;
#pragma unroll
        for (int k = 0; k < 4; k++) {
            float4 p = P4[lane + 32*k];
            s += p.x + p.y + p.z + p.w;
        }
        s = warp_sum(s);
        if (lane == 0) out[OFF_W + row] = s;
    }
}

extern "C" void kernel_launch(void* const* d_in, const int* in_sizes, int n_in,
                              void* d_out, int out_size)
{
    const float* U0  = (const float*)d_in[0];
    const float* U1  = (const float*)d_in[1];
    const float* U2  = (const float*)d_in[2];
    const float* S   = (const float*)d_in[3];
    const float* w   = (const float*)d_in[4];
    const float* tn  = (const float*)d_in[5];
    const float* obs = (const float*)d_in[6];
    const int*   idx = (const int*)d_in[7];
    float* out = (float*)d_out;

    const int smem_bytes = SMEM_FLOATS * (int)sizeof(float);
    cudaFuncSetAttribute(fwd_kernel, cudaFuncAttributeMaxDynamicSharedMemorySize, smem_bytes);

    fwd_kernel<<<NBLK, 512, smem_bytes>>>(U0, U1, U2, S, w, tn, obs, idx, out);
    red_kernel<<<2*NMF + 32, 512>>>(out);
}

// round 6
// speedup vs baseline: 1.2134x; 1.2134x over previous
#include <cuda_runtime.h>

// Problem constants
#define NB    512       // batch B
#define NMF   256       // M features
#define INDIM 50
#define SROW  51        // padded S row (conflict-free smem)
#define OFF_U 512
#define OFF_S 25088     // 512 + 512*48
#define OFF_W 37888     // OFF_S + 256*50
#define G     4         // batch elements per fwd block
#define NBLK  (NB/G)    // 128 fwd blocks
#define PART  13312     // per-block partial: 50*256 (grad_S, j-major) + 256 gc + 256 gs

__device__ float g_part[NBLK * PART];

__device__ __forceinline__ float warp_sum(float v) {
#pragma unroll
    for (int o = 16; o; o >>= 1) v += __shfl_down_sync(0xffffffffu, v, o);
    return v;
}
__device__ __forceinline__ float xor_sum(float v) {
#pragma unroll
    for (int o = 16; o; o >>= 1) v += __shfl_xor_sync(0xffffffffu, v, o);
    return v;
}

// smem floats: S[256*51] | inp[4*64] | red[4*64 + 16] | e/et/ex/gc/gs [4*256] each
#define SMEM_FLOATS (NMF*SROW + 256 + 272 + 5*1024)

// 512 threads: half = t>>8 handles g in {2*half, 2*half+1}; m = t & 255.
__global__ __launch_bounds__(512) void fwd_kernel(
    const float* __restrict__ U0, const float* __restrict__ U1,
    const float* __restrict__ U2, const float* __restrict__ S,
    const float* __restrict__ w,  const float* __restrict__ tn,
    const float* __restrict__ obs, const int* __restrict__ idx,
    float* __restrict__ out)
{
    extern __shared__ float sm[];
    float* Ssm  = sm;                    // 256*51
    float* inp  = Ssm + NMF*SROW;        // 4*64
    float* red  = inp + 256;             // 4 stages * 64 ; [256..259] = lamA per g
    float* e_sm  = red + 272;            // [4][256]
    float* et_sm = e_sm  + 1024;
    float* ex_sm = et_sm + 1024;
    float* gc_sm = ex_sm + 1024;
    float* gs_sm = gc_sm + 1024;

    const int b0   = blockIdx.x * G;
    const int t    = threadIdx.x;
    const int lane = t & 31;
    const int wid  = t >> 5;             // 0..15
    const int m    = t & 255;
    const int half = t >> 8;             // 0 or 1
    const int w8   = wid & 7;
    const int g0   = half * 2;

    // Load S via float4, scatter into padded smem rows
    {
        const float4* S4 = (const float4*)S;
        for (int i = t; i < (NMF*INDIM)/4; i += 512) {
            float4 v = S4[i];
            int base = i * 4;
#pragma unroll
            for (int c = 0; c < 4; c++) {
                int id = base + c;
                int mm = id / INDIM;
                int jj = id - mm*INDIM;
                float vc = (c == 0) ? v.x : (c == 1) ? v.y : (c == 2) ? v.z : v.w;
                Ssm[mm*SROW + jj] = vc;
            }
        }
    }
    // Gather Uvec (4 b x 48 values)
    if (t < G*48) {
        int gg = t / 48, j = t - gg*48;
        int v = j >> 4, r = j & 15;
        int iv = idx[(b0 + gg)*3 + v];
        const float* Uv = (v == 0) ? U0 : (v == 1) ? U1 : U2;
        inp[gg*64 + 2 + j] = Uv[iv*16 + r];
    }
    __syncthreads();

    const float wc = w[m], ws = w[256 + m];
    const float s0 = Ssm[m*SROW + 0], s1 = Ssm[m*SROW + 1];

    float scaleT[2], obsg[2], beta[2], phiU[2];
#pragma unroll
    for (int gi = 0; gi < 2; gi++) {
        const int g = g0 + gi;
        scaleT[gi] = tn[b0 + g];
        obsg[gi]   = obs[b0 + g];
        const float* inpg = inp + g*64;
        float bt = 0.f;
        if (lane < 16) bt = inpg[2 + lane] * inpg[18 + lane] * inpg[34 + lane];
        beta[gi] = xor_sum(bt);
        float acc = 0.f;
#pragma unroll
        for (int j = 2; j < INDIM; j++) acc = fmaf(Ssm[m*SROW + j], inpg[j], acc);
        phiU[gi] = acc;
    }

    // ---- RK4 stages (t = 0, 0.5, 0.5, 1 ; h = 1), state in registers ----
    float in0[2] = {0.f, 0.f};
    float in1[2] = {beta[0], beta[1]};
    float cpS[4][2], spS[4][2], kS[4][2], JS[4][2], xS[4][2], tS[4][2];
#pragma unroll
    for (int i = 0; i < 4; i++) {
        float fp[2], jp[2];
#pragma unroll
        for (int gi = 0; gi < 2; gi++) {
            xS[i][gi] = in1[gi]; tS[i][gi] = in0[gi];
            float phi = phiU[gi] + s0*in0[gi] + s1*in1[gi];
            float cp, sp;
            __sincosf(phi, &sp, &cp);
            cpS[i][gi] = cp; spS[i][gi] = sp;
            fp[gi] = xor_sum(cp*wc + sp*ws);
            jp[gi] = xor_sum((cp*ws - sp*wc) * s1);
        }
        if (lane == 0) {
#pragma unroll
            for (int gi = 0; gi < 2; gi++) {
                const int g = g0 + gi;
                red[i*64 + g*8 + w8]      = fp[gi];
                red[i*64 + 32 + g*8 + w8] = jp[gi];
            }
        }
        __syncthreads();
#pragma unroll
        for (int gi = 0; gi < 2; gi++) {
            const int g = g0 + gi;
            float F = 0.f, JJ = 0.f;
#pragma unroll
            for (int q = 0; q < 8; q++) {
                F  += red[i*64 + g*8 + q];
                JJ += red[i*64 + 32 + g*8 + q];
            }
            float k = scaleT[gi] * F;
            kS[i][gi] = k; JS[i][gi] = scaleT[gi] * JJ;
            if (i < 2)      { in1[gi] = beta[gi] + 0.5f*k; in0[gi] = scaleT[gi]*0.5f; }
            else if (i == 2){ in1[gi] = beta[gi] + k;      in0[gi] = scaleT[gi]; }
        }
    }

    // Discrete-adjoint RK4 coefficients + pass 2 (registers only)
#pragma unroll
    for (int gi = 0; gi < 2; gi++) {
        const int g = g0 + gi;
        const float J1 = JS[0][gi], J2 = JS[1][gi], J3 = JS[2][gi], J4 = JS[3][gi];
        const float xT  = beta[gi] + (kS[0][gi] + 2.f*kS[1][gi] + 2.f*kS[2][gi] + kS[3][gi]) * (1.f/6.f);
        const float lam = (xT - obsg[gi]) * (1.f/512.f);
        const float a1 = J1;
        const float a2 = J2*(1.f + 0.5f*a1);
        const float a3 = J3*(1.f + 0.5f*a2);
        const float a4 = J4*(1.f + a3);
        const float A  = 1.f + (a1 + 2.f*a2 + 2.f*a3 + a4) * (1.f/6.f);
        const float ls = lam * scaleT[gi];
        float ch[4];
        ch[0] = ls * (1.f + J2 + 0.5f*J3*J2 + 0.25f*J4*J3*J2) * (1.f/6.f);
        ch[1] = ls * (2.f + J3 + 0.5f*J4*J3) * (1.f/6.f);
        ch[2] = ls * (2.f + J4) * (1.f/6.f);
        ch[3] = ls * (1.f/6.f);
        const float lamA = lam * A;
        if (m == 0) {
            out[b0 + g] = lamA;          // grad wrt beta (diagonal)
            red[256 + g] = lamA;
        }
        float e = 0.f, et = 0.f, ex = 0.f, gc = 0.f, gs = 0.f;
#pragma unroll
        for (int i = 0; i < 4; i++) {
            float d  = cpS[i][gi]*ws - spS[i][gi]*wc;
            float cd = ch[i] * d;
            e  += cd;
            et += cd * tS[i][gi];
            ex += cd * xS[i][gi];
            gc += ch[i] * cpS[i][gi];
            gs += ch[i] * spS[i][gi];
        }
        e_sm [g*256 + m] = e;
        et_sm[g*256 + m] = et;
        ex_sm[g*256 + m] = ex;
        gc_sm[g*256 + m] = gc;
        gs_sm[g*256 + m] = gs;
    }
    __syncthreads();

    // ---- per-block partial grad_S (j-major) + grad_w ----
    {
        const long bp = (long)blockIdx.x * PART;
        const float eg0 = e_sm[m], eg1 = e_sm[256 + m], eg2 = e_sm[512 + m], eg3 = e_sm[768 + m];
        if (half == 0) {
            g_part[bp + 0*256 + m] = et_sm[m] + et_sm[256+m] + et_sm[512+m] + et_sm[768+m];
            g_part[bp + 1*256 + m] = ex_sm[m] + ex_sm[256+m] + ex_sm[512+m] + ex_sm[768+m];
#pragma unroll
            for (int c = 2; c < 25; c++) {
                float s = eg0*inp[c] + eg1*inp[64+c] + eg2*inp[128+c] + eg3*inp[192+c];
                g_part[bp + c*256 + m] = s;
            }
            g_part[bp + 12800 + m] = gc_sm[m] + gc_sm[256+m] + gc_sm[512+m] + gc_sm[768+m];
        } else {
#pragma unroll
            for (int c = 25; c < 50; c++) {
                float s = eg0*inp[c] + eg1*inp[64+c] + eg2*inp[128+c] + eg3*inp[192+c];
                g_part[bp + c*256 + m] = s;
            }
            g_part[bp + 13056 + m] = gs_sm[m] + gs_sm[256+m] + gs_sm[512+m] + gs_sm[768+m];
        }
    }

    // ---- per-b Uvec gradient: sum_m e_m * S[m, 2+j] + beta-chain term ----
    // 16 warps x 12 tasks = 4 g x 48 j
    {
#pragma unroll
        for (int q = 0; q < 12; q++) {
            int T = wid*12 + q;
            int g = T / 48, j = T - g*48;
            const float* eg = e_sm + g*256;
            float s = 0.f;
#pragma unroll
            for (int k = 0; k < 8; k++) {
                int mm = lane + 32*k;
                s += eg[mm] * Ssm[mm*SROW + 2 + j];
            }
            s = warp_sum(s);
            if (lane == 0) {
                const float* inpg = inp + g*64;
                int v = j >> 4, r = j & 15;
                float u0 = inpg[2 + r], u1 = inpg[18 + r], u2 = inpg[34 + r];
                float pe = (v == 0) ? u1*u2 : (v == 1) ? u0*u2 : u0*u1;
                out[OFF_U + (b0 + g)*48 + j] = s + red[256 + g] * pe;
            }
        }
    }
}

// Stage 2: sum 128 per-block partials for each of 13312 outputs.
__global__ __launch_bounds__(256) void red2_kernel(float* __restrict__ out)
{
    const int i = blockIdx.x * 256 + threadIdx.x;   // 52 blocks x 256 = 13312
    const float* P = g_part + i;
    float s0 = 0.f, s1 = 0.f, s2 = 0.f, s3 = 0.f;
#pragma unroll 8
    for (int p = 0; p < 128; p += 4) {
        s0 += P[(p + 0)*PART];
        s1 += P[(p + 1)*PART];
        s2 += P[(p + 2)*PART];
        s3 += P[(p + 3)*PART];
    }
    float s = (s0 + s1) + (s2 + s3);
    if (i < 12800) {
        int c = i >> 8, m = i & 255;
        out[OFF_S + m*INDIM + c] = s;
    } else if (i < 13056) {
        out[OFF_W + (i - 12800)] = s;
    } else {
        out[OFF_W + 256 + (i - 13056)] = s;
    }
}

extern "C" void kernel_launch(void* const* d_in, const int* in_sizes, int n_in,
                              void* d_out, int out_size)
{
    const float* U0  = (const float*)d_in[0];
    const float* U1  = (const float*)d_in[1];
    const float* U2  = (const float*)d_in[2];
    const float* S   = (const float*)d_in[3];
    const float* w   = (const float*)d_in[4];
    const float* tn  = (const float*)d_in[5];
    const float* obs = (const float*)d_in[6];
    const int*   idx = (const int*)d_in[7];
    float* out = (float*)d_out;

    const int smem_bytes = SMEM_FLOATS * (int)sizeof(float);
    cudaFuncSetAttribute(fwd_kernel, cudaFuncAttributeMaxDynamicSharedMemorySize, smem_bytes);

    fwd_kernel<<<NBLK, 512, smem_bytes>>>(U0, U1, U2, S, w, tn, obs, idx, out);
    red2_kernel<<<52, 256>>>(out);
}

// round 7
// speedup vs baseline: 1.2703x; 1.0468x over previous
#include <cuda_runtime.h>

// Problem constants
#define NB    512       // batch B
#define NMF   256       // M features
#define INDIM 50
#define SROW  51        // padded S row (conflict-free smem)
#define OFF_U 512
#define OFF_S 25088     // 512 + 512*48
#define OFF_W 37888     // OFF_S + 256*50
#define G     4         // batch elements per fwd block
#define NBLK  (NB/G)    // 128 fwd blocks
#define PART  13312     // per-block partial: 50*256 (grad_S, j-major) + 256 gc + 256 gs

__device__ float g_part[NBLK * PART];

__device__ __forceinline__ float warp_sum(float v) {
#pragma unroll
    for (int o = 16; o; o >>= 1) v += __shfl_down_sync(0xffffffffu, v, o);
    return v;
}
__device__ __forceinline__ float xor_sum(float v) {
#pragma unroll
    for (int o = 16; o; o >>= 1) v += __shfl_xor_sync(0xffffffffu, v, o);
    return v;
}

// smem floats: S[256*51] | inp[4*64] | red[4*64 + 16] | e/et/ex/gc/gs [4*256] each
#define SMEM_FLOATS (NMF*SROW + 256 + 272 + 5*1024)

// 512 threads: half = t>>8 handles g in {2*half, 2*half+1}; m = t & 255.
__global__ __launch_bounds__(512) void fwd_kernel(
    const float* __restrict__ U0, const float* __restrict__ U1,
    const float* __restrict__ U2, const float* __restrict__ S,
    const float* __restrict__ w,  const float* __restrict__ tn,
    const float* __restrict__ obs, const int* __restrict__ idx,
    float* __restrict__ out)
{
    extern __shared__ float sm[];
    float* Ssm  = sm;                    // 256*51
    float* inp  = Ssm + NMF*SROW;        // 4*64
    float* red  = inp + 256;             // 4 stages * 64 ; [256..259] = lamA per g
    float* e_sm  = red + 272;            // [4][256]
    float* et_sm = e_sm  + 1024;
    float* ex_sm = et_sm + 1024;
    float* gc_sm = ex_sm + 1024;
    float* gs_sm = gc_sm + 1024;

    const int b0   = blockIdx.x * G;
    const int t    = threadIdx.x;
    const int lane = t & 31;
    const int wid  = t >> 5;             // 0..15
    const int m    = t & 255;
    const int half = t >> 8;             // 0 or 1
    const int w8   = wid & 7;
    const int g0   = half * 2;

    // Load S via float4, scatter into padded smem rows
    {
        const float4* S4 = (const float4*)S;
        for (int i = t; i < (NMF*INDIM)/4; i += 512) {
            float4 v = S4[i];
            int base = i * 4;
#pragma unroll
            for (int c = 0; c < 4; c++) {
                int id = base + c;
                int mm = id / INDIM;
                int jj = id - mm*INDIM;
                float vc = (c == 0) ? v.x : (c == 1) ? v.y : (c == 2) ? v.z : v.w;
                Ssm[mm*SROW + jj] = vc;
            }
        }
    }
    // Gather Uvec (4 b x 48 values)
    if (t < G*48) {
        int gg = t / 48, j = t - gg*48;
        int v = j >> 4, r = j & 15;
        int iv = idx[(b0 + gg)*3 + v];
        const float* Uv = (v == 0) ? U0 : (v == 1) ? U1 : U2;
        inp[gg*64 + 2 + j] = Uv[iv*16 + r];
    }
    __syncthreads();

    const float wc = w[m], ws = w[256 + m];
    const float s0 = Ssm[m*SROW + 0], s1 = Ssm[m*SROW + 1];

    float scaleT[2], obsg[2], beta[2], phiU[2];
#pragma unroll
    for (int gi = 0; gi < 2; gi++) {
        const int g = g0 + gi;
        scaleT[gi] = tn[b0 + g];
        obsg[gi]   = obs[b0 + g];
        const float* inpg = inp + g*64;
        float bt = 0.f;
        if (lane < 16) bt = inpg[2 + lane] * inpg[18 + lane] * inpg[34 + lane];
        beta[gi] = xor_sum(bt);
        float acc = 0.f;
#pragma unroll
        for (int j = 2; j < INDIM; j++) acc = fmaf(Ssm[m*SROW + j], inpg[j], acc);
        phiU[gi] = acc;
    }

    // ---- RK4 stages (t = 0, 0.5, 0.5, 1 ; h = 1), state in registers ----
    float in0[2] = {0.f, 0.f};
    float in1[2] = {beta[0], beta[1]};
    float cpS[4][2], spS[4][2], kS[4][2], JS[4][2], xS[4][2], tS[4][2];
#pragma unroll
    for (int i = 0; i < 4; i++) {
        float fp[2], jp[2];
#pragma unroll
        for (int gi = 0; gi < 2; gi++) {
            xS[i][gi] = in1[gi]; tS[i][gi] = in0[gi];
            float phi = phiU[gi] + s0*in0[gi] + s1*in1[gi];
            float cp, sp;
            __sincosf(phi, &sp, &cp);
            cpS[i][gi] = cp; spS[i][gi] = sp;
            fp[gi] = xor_sum(cp*wc + sp*ws);
            jp[gi] = xor_sum((cp*ws - sp*wc) * s1);
        }
        if (lane == 0) {
#pragma unroll
            for (int gi = 0; gi < 2; gi++) {
                const int g = g0 + gi;
                red[i*64 + g*8 + w8]      = fp[gi];
                red[i*64 + 32 + g*8 + w8] = jp[gi];
            }
        }
        __syncthreads();
#pragma unroll
        for (int gi = 0; gi < 2; gi++) {
            const int g = g0 + gi;
            float F = 0.f, JJ = 0.f;
#pragma unroll
            for (int q = 0; q < 8; q++) {
                F  += red[i*64 + g*8 + q];
                JJ += red[i*64 + 32 + g*8 + q];
            }
            float k = scaleT[gi] * F;
            kS[i][gi] = k; JS[i][gi] = scaleT[gi] * JJ;
            if (i < 2)      { in1[gi] = beta[gi] + 0.5f*k; in0[gi] = scaleT[gi]*0.5f; }
            else if (i == 2){ in1[gi] = beta[gi] + k;      in0[gi] = scaleT[gi]; }
        }
    }

    // Discrete-adjoint RK4 coefficients + pass 2 (registers only)
#pragma unroll
    for (int gi = 0; gi < 2; gi++) {
        const int g = g0 + gi;
        const float J1 = JS[0][gi], J2 = JS[1][gi], J3 = JS[2][gi], J4 = JS[3][gi];
        const float xT  = beta[gi] + (kS[0][gi] + 2.f*kS[1][gi] + 2.f*kS[2][gi] + kS[3][gi]) * (1.f/6.f);
        const float lam = (xT - obsg[gi]) * (1.f/512.f);
        const float a1 = J1;
        const float a2 = J2*(1.f + 0.5f*a1);
        const float a3 = J3*(1.f + 0.5f*a2);
        const float a4 = J4*(1.f + a3);
        const float A  = 1.f + (a1 + 2.f*a2 + 2.f*a3 + a4) * (1.f/6.f);
        const float ls = lam * scaleT[gi];
        float ch[4];
        ch[0] = ls * (1.f + J2 + 0.5f*J3*J2 + 0.25f*J4*J3*J2) * (1.f/6.f);
        ch[1] = ls * (2.f + J3 + 0.5f*J4*J3) * (1.f/6.f);
        ch[2] = ls * (2.f + J4) * (1.f/6.f);
        ch[3] = ls * (1.f/6.f);
        const float lamA = lam * A;
        if (m == 0) {
            out[b0 + g] = lamA;          // grad wrt beta (diagonal)
            red[256 + g] = lamA;
        }
        float e = 0.f, et = 0.f, ex = 0.f, gc = 0.f, gs = 0.f;
#pragma unroll
        for (int i = 0; i < 4; i++) {
            float d  = cpS[i][gi]*ws - spS[i][gi]*wc;
            float cd = ch[i] * d;
            e  += cd;
            et += cd * tS[i][gi];
            ex += cd * xS[i][gi];
            gc += ch[i] * cpS[i][gi];
            gs += ch[i] * spS[i][gi];
        }
        e_sm [g*256 + m] = e;
        et_sm[g*256 + m] = et;
        ex_sm[g*256 + m] = ex;
        gc_sm[g*256 + m] = gc;
        gs_sm[g*256 + m] = gs;
    }
    __syncthreads();

    // ---- per-block partial grad_S (j-major) + grad_w ----
    {
        const long bp = (long)blockIdx.x * PART;
        const float eg0 = e_sm[m], eg1 = e_sm[256 + m], eg2 = e_sm[512 + m], eg3 = e_sm[768 + m];
        if (half == 0) {
            g_part[bp + 0*256 + m] = et_sm[m] + et_sm[256+m] + et_sm[512+m] + et_sm[768+m];
            g_part[bp + 1*256 + m] = ex_sm[m] + ex_sm[256+m] + ex_sm[512+m] + ex_sm[768+m];
#pragma unroll
            for (int c = 2; c < 25; c++) {
                float s = eg0*inp[c] + eg1*inp[64+c] + eg2*inp[128+c] + eg3*inp[192+c];
                g_part[bp + c*256 + m] = s;
            }
            g_part[bp + 12800 + m] = gc_sm[m] + gc_sm[256+m] + gc_sm[512+m] + gc_sm[768+m];
        } else {
#pragma unroll
            for (int c = 25; c < 50; c++) {
                float s = eg0*inp[c] + eg1*inp[64+c] + eg2*inp[128+c] + eg3*inp[192+c];
                g_part[bp + c*256 + m] = s;
            }
            g_part[bp + 13056 + m] = gs_sm[m] + gs_sm[256+m] + gs_sm[512+m] + gs_sm[768+m];
        }
    }

    // ---- per-b Uvec gradient: sum_m e_m * S[m, 2+j] + beta-chain term ----
    // 16 warps x 12 tasks = 4 g x 48 j
    {
#pragma unroll
        for (int q = 0; q < 12; q++) {
            int T = wid*12 + q;
            int g = T / 48, j = T - g*48;
            const float* eg = e_sm + g*256;
            float s = 0.f;
#pragma unroll
            for (int k = 0; k < 8; k++) {
                int mm = lane + 32*k;
                s += eg[mm] * Ssm[mm*SROW + 2 + j];
            }
            s = warp_sum(s);
            if (lane == 0) {
                const float* inpg = inp + g*64;
                int v = j >> 4, r = j & 15;
                float u0 = inpg[2 + r], u1 = inpg[18 + r], u2 = inpg[34 + r];
                float pe = (v == 0) ? u1*u2 : (v == 1) ? u0*u2 : u0*u1;
                out[OFF_U + (b0 + g)*48 + j] = s + red[256 + g] * pe;
            }
        }
    }
}

// Stage 2: sum 128 per-block partials for each of 13312 outputs.
// Parallelized: thread = (p-group q of 8, output-quad Q). Each thread sums 16
// partials for 4 consecutive outputs via float4; smem tree combines the 8 groups.
// Block: 256 threads = 8 q x 32 quads (128 outputs). Grid: 13312/128 = 104.
__global__ __launch_bounds__(256) void red2_kernel(float* __restrict__ out)
{
    __shared__ float4 redq[8][32];
    const int t  = threadIdx.x;
    const int q  = t >> 5;             // 0..7  (p-group)
    const int il = t & 31;             // quad within block
    const int Q  = blockIdx.x * 32 + il;   // global output quad (0..3327)
    const float* P = g_part + 4*Q;

    float4 a0 = make_float4(0.f,0.f,0.f,0.f), a1 = a0, a2 = a0, a3 = a0;
#pragma unroll
    for (int k = 0; k < 4; k++) {
        const int p = q*16 + k*4;
        float4 v0 = *(const float4*)(P + (long)(p + 0)*PART);
        float4 v1 = *(const float4*)(P + (long)(p + 1)*PART);
        float4 v2 = *(const float4*)(P + (long)(p + 2)*PART);
        float4 v3 = *(const float4*)(P + (long)(p + 3)*PART);
        a0.x += v0.x; a0.y += v0.y; a0.z += v0.z; a0.w += v0.w;
        a1.x += v1.x; a1.y += v1.y; a1.z += v1.z; a1.w += v1.w;
        a2.x += v2.x; a2.y += v2.y; a2.z += v2.z; a2.w += v2.w;
        a3.x += v3.x; a3.y += v3.y; a3.z += v3.z; a3.w += v3.w;
    }
    float4 a;
    a.x = (a0.x + a1.x) + (a2.x + a3.x);
    a.y = (a0.y + a1.y) + (a2.y + a3.y);
    a.z = (a0.z + a1.z) + (a2.z + a3.z);
    a.w = (a0.w + a1.w) + (a2.w + a3.w);
    redq[q][il] = a;
    __syncthreads();

    if (q == 0) {
        float4 s = redq[0][il];
#pragma unroll
        for (int qq = 1; qq < 8; qq++) {
            float4 v = redq[qq][il];
            s.x += v.x; s.y += v.y; s.z += v.z; s.w += v.w;
        }
        const float sv[4] = {s.x, s.y, s.z, s.w};
#pragma unroll
        for (int c4 = 0; c4 < 4; c4++) {
            int i = 4*Q + c4;
            if (i < 12800) {
                int c = i >> 8, m = i & 255;
                out[OFF_S + m*INDIM + c] = sv[c4];
            } else if (i < 13056) {
                out[OFF_W + (i - 12800)] = sv[c4];
            } else {
                out[OFF_W + 256 + (i - 13056)] = sv[c4];
            }
        }
    }
}

extern "C" void kernel_launch(void* const* d_in, const int* in_sizes, int n_in,
                              void* d_out, int out_size)
{
    const float* U0  = (const float*)d_in[0];
    const float* U1  = (const float*)d_in[1];
    const float* U2  = (const float*)d_in[2];
    const float* S   = (const float*)d_in[3];
    const float* w   = (const float*)d_in[4];
    const float* tn  = (const float*)d_in[5];
    const float* obs = (const float*)d_in[6];
    const int*   idx = (const int*)d_in[7];
    float* out = (float*)d_out;

    const int smem_bytes = SMEM_FLOATS * (int)sizeof(float);
    cudaFuncSetAttribute(fwd_kernel, cudaFuncAttributeMaxDynamicSharedMemorySize, smem_bytes);

    fwd_kernel<<<NBLK, 512, smem_bytes>>>(U0, U1, U2, S, w, tn, obs, idx, out);
    red2_kernel<<<104, 256>>>(out);
}

// round 8
// speedup vs baseline: 1.3558x; 1.0673x over previous
#include <cuda_runtime.h>

// Problem constants
#define NB    512       // batch B
#define NMF   256       // M features
#define INDIM 50
#define SROW  51        // padded S row (conflict-free smem)
#define OFF_U 512
#define OFF_S 25088     // 512 + 512*48
#define OFF_W 37888     // OFF_S + 256*50
#define G     4         // batch elements per fwd block
#define NBLK  (NB/G)    // 128 fwd blocks
#define PART  13312     // per-block partial: 50*256 (grad_S, j-major) + 256 gc + 256 gs

__device__ float g_part[NBLK * PART];

__device__ __forceinline__ float warp_sum(float v) {
#pragma unroll
    for (int o = 16; o; o >>= 1) v += __shfl_down_sync(0xffffffffu, v, o);
    return v;
}
__device__ __forceinline__ float xor_sum(float v) {
#pragma unroll
    for (int o = 16; o; o >>= 1) v += __shfl_xor_sync(0xffffffffu, v, o);
    return v;
}
// Named barrier over one 256-thread half (ids 1 and 2)
#define BAR_HALF(h) asm volatile("bar.sync %0, 256;" :: "r"(1 + (h)) : "memory")

// smem floats: S[256*51] | inp[4*64] | red[4*64 + 16] | e/et/ex/gc/gs [4*256] each
#define SMEM_FLOATS (NMF*SROW + 256 + 272 + 5*1024)

// 512 threads: half = t>>8 handles g in {2*half, 2*half+1}; m = t & 255.
__global__ __launch_bounds__(512) void fwd_kernel(
    const float* __restrict__ U0, const float* __restrict__ U1,
    const float* __restrict__ U2, const float* __restrict__ S,
    const float* __restrict__ w,  const float* __restrict__ tn,
    const float* __restrict__ obs, const int* __restrict__ idx,
    float* __restrict__ out)
{
    extern __shared__ float sm[];
    float* Ssm  = sm;                    // 256*51
    float* inp  = Ssm + NMF*SROW;        // 4*64
    float* red  = inp + 256;             // 4 stages * 64 ; [256..259] = lamA per g
    float* e_sm  = red + 272;            // [4][256]
    float* et_sm = e_sm  + 1024;
    float* ex_sm = et_sm + 1024;
    float* gc_sm = ex_sm + 1024;
    float* gs_sm = gc_sm + 1024;

    const int b0   = blockIdx.x * G;
    const int t    = threadIdx.x;
    const int lane = t & 31;
    const int wid  = t >> 5;             // 0..15
    const int m    = t & 255;
    const int half = t >> 8;             // 0 or 1
    const int w8   = wid & 7;
    const int g0   = half * 2;

    // Load S via float4, scatter into padded smem rows
    {
        const float4* S4 = (const float4*)S;
        for (int i = t; i < (NMF*INDIM)/4; i += 512) {
            float4 v = S4[i];
            int base = i * 4;
#pragma unroll
            for (int c = 0; c < 4; c++) {
                int id = base + c;
                int mm = id / INDIM;
                int jj = id - mm*INDIM;
                float vc = (c == 0) ? v.x : (c == 1) ? v.y : (c == 2) ? v.z : v.w;
                Ssm[mm*SROW + jj] = vc;
            }
        }
    }
    // Gather Uvec (4 b x 48 values)
    if (t < G*48) {
        int gg = t / 48, j = t - gg*48;
        int v = j >> 4, r = j & 15;
        int iv = idx[(b0 + gg)*3 + v];
        const float* Uv = (v == 0) ? U0 : (v == 1) ? U1 : U2;
        inp[gg*64 + 2 + j] = Uv[iv*16 + r];
    }
    __syncthreads();

    const float wc = w[m], ws = w[256 + m];
    const float s0 = Ssm[m*SROW + 0], s1 = Ssm[m*SROW + 1];

    float scaleT[2], obsg[2], beta[2], phiU[2];
#pragma unroll
    for (int gi = 0; gi < 2; gi++) {
        const int g = g0 + gi;
        scaleT[gi] = tn[b0 + g];
        obsg[gi]   = obs[b0 + g];
        const float* inpg = inp + g*64;
        float bt = 0.f;
        if (lane < 16) bt = inpg[2 + lane] * inpg[18 + lane] * inpg[34 + lane];
        beta[gi] = xor_sum(bt);
        float acc = 0.f;
#pragma unroll
        for (int j = 2; j < INDIM; j++) acc = fmaf(Ssm[m*SROW + j], inpg[j], acc);
        phiU[gi] = acc;
    }

    // ---- RK4 stages (t = 0, 0.5, 0.5, 1 ; h = 1), state in registers ----
    // Per-stage reduction only spans this half's 8 warps -> named barrier.
    float in0[2] = {0.f, 0.f};
    float in1[2] = {beta[0], beta[1]};
    float cpS[4][2], spS[4][2], kS[4][2], JS[4][2], xS[4][2], tS[4][2];
#pragma unroll
    for (int i = 0; i < 4; i++) {
        float fp[2], jp[2];
#pragma unroll
        for (int gi = 0; gi < 2; gi++) {
            xS[i][gi] = in1[gi]; tS[i][gi] = in0[gi];
            float phi = phiU[gi] + s0*in0[gi] + s1*in1[gi];
            float cp, sp;
            __sincosf(phi, &sp, &cp);
            cpS[i][gi] = cp; spS[i][gi] = sp;
            fp[gi] = xor_sum(cp*wc + sp*ws);
            jp[gi] = xor_sum((cp*ws - sp*wc) * s1);
        }
        if (lane == 0) {
#pragma unroll
            for (int gi = 0; gi < 2; gi++) {
                const int g = g0 + gi;
                red[i*64 + g*8 + w8]      = fp[gi];
                red[i*64 + 32 + g*8 + w8] = jp[gi];
            }
        }
        BAR_HALF(half);
#pragma unroll
        for (int gi = 0; gi < 2; gi++) {
            const int g = g0 + gi;
            float F = 0.f, JJ = 0.f;
#pragma unroll
            for (int q = 0; q < 8; q++) {
                F  += red[i*64 + g*8 + q];
                JJ += red[i*64 + 32 + g*8 + q];
            }
            float k = scaleT[gi] * F;
            kS[i][gi] = k; JS[i][gi] = scaleT[gi] * JJ;
            if (i < 2)      { in1[gi] = beta[gi] + 0.5f*k; in0[gi] = scaleT[gi]*0.5f; }
            else if (i == 2){ in1[gi] = beta[gi] + k;      in0[gi] = scaleT[gi]; }
        }
    }

    // Discrete-adjoint RK4 coefficients + pass 2 (registers only)
#pragma unroll
    for (int gi = 0; gi < 2; gi++) {
        const int g = g0 + gi;
        const float J1 = JS[0][gi], J2 = JS[1][gi], J3 = JS[2][gi], J4 = JS[3][gi];
        const float xT  = beta[gi] + (kS[0][gi] + 2.f*kS[1][gi] + 2.f*kS[2][gi] + kS[3][gi]) * (1.f/6.f);
        const float lam = (xT - obsg[gi]) * (1.f/512.f);
        const float a1 = J1;
        const float a2 = J2*(1.f + 0.5f*a1);
        const float a3 = J3*(1.f + 0.5f*a2);
        const float a4 = J4*(1.f + a3);
        const float A  = 1.f + (a1 + 2.f*a2 + 2.f*a3 + a4) * (1.f/6.f);
        const float ls = lam * scaleT[gi];
        float ch[4];
        ch[0] = ls * (1.f + J2 + 0.5f*J3*J2 + 0.25f*J4*J3*J2) * (1.f/6.f);
        ch[1] = ls * (2.f + J3 + 0.5f*J4*J3) * (1.f/6.f);
        ch[2] = ls * (2.f + J4) * (1.f/6.f);
        ch[3] = ls * (1.f/6.f);
        const float lamA = lam * A;
        if (m == 0) {
            out[b0 + g] = lamA;          // grad wrt beta (diagonal)
            red[256 + g] = lamA;
        }
        float e = 0.f, et = 0.f, ex = 0.f, gc = 0.f, gs = 0.f;
#pragma unroll
        for (int i = 0; i < 4; i++) {
            float d  = cpS[i][gi]*ws - spS[i][gi]*wc;
            float cd = ch[i] * d;
            e  += cd;
            et += cd * tS[i][gi];
            ex += cd * xS[i][gi];
            gc += ch[i] * cpS[i][gi];
            gs += ch[i] * spS[i][gi];
        }
        e_sm [g*256 + m] = e;
        et_sm[g*256 + m] = et;
        ex_sm[g*256 + m] = ex;
        gc_sm[g*256 + m] = gc;
        gs_sm[g*256 + m] = gs;
    }

    // ---- per-b Uvec gradient (half-local: g of this half only) ----
    // Needs this half's e_sm rows (written by this half's 8 warps).
    BAR_HALF(half);
    {
        // 8 warps of this half cover 2 g x 48 j = 96 tasks -> 12 per warp
#pragma unroll
        for (int q = 0; q < 12; q++) {
            int T = w8*12 + q;                  // 0..95
            int gi = T / 48, j = T - gi*48;
            const int g = g0 + gi;
            const float* eg = e_sm + g*256;
            float s = 0.f;
#pragma unroll
            for (int k = 0; k < 8; k++) {
                int mm = lane + 32*k;
                s += eg[mm] * Ssm[mm*SROW + 2 + j];
            }
            s = warp_sum(s);
            if (lane == 0) {
                const float* inpg = inp + g*64;
                int v = j >> 4, r = j & 15;
                float u0 = inpg[2 + r], u1 = inpg[18 + r], u2 = inpg[34 + r];
                float pe = (v == 0) ? u1*u2 : (v == 1) ? u0*u2 : u0*u1;
                out[OFF_U + (b0 + g)*48 + j] = s + red[256 + g] * pe;
            }
        }
    }

    // ---- per-block partial grad_S (j-major) + grad_w (cross-half reads) ----
    __syncthreads();
    {
        const long bp = (long)blockIdx.x * PART;
        const float eg0 = e_sm[m], eg1 = e_sm[256 + m], eg2 = e_sm[512 + m], eg3 = e_sm[768 + m];
        if (half == 0) {
            g_part[bp + 0*256 + m] = et_sm[m] + et_sm[256+m] + et_sm[512+m] + et_sm[768+m];
            g_part[bp + 1*256 + m] = ex_sm[m] + ex_sm[256+m] + ex_sm[512+m] + ex_sm[768+m];
#pragma unroll
            for (int c = 2; c < 25; c++) {
                float s = eg0*inp[c] + eg1*inp[64+c] + eg2*inp[128+c] + eg3*inp[192+c];
                g_part[bp + c*256 + m] = s;
            }
            g_part[bp + 12800 + m] = gc_sm[m] + gc_sm[256+m] + gc_sm[512+m] + gc_sm[768+m];
        } else {
#pragma unroll
            for (int c = 25; c < 50; c++) {
                float s = eg0*inp[c] + eg1*inp[64+c] + eg2*inp[128+c] + eg3*inp[192+c];
                g_part[bp + c*256 + m] = s;
            }
            g_part[bp + 13056 + m] = gs_sm[m] + gs_sm[256+m] + gs_sm[512+m] + gs_sm[768+m];
        }
    }
}

// Stage 2: sum 128 per-block partials for each of 13312 outputs.
// thread = (p-group pg of 32, quad ql of 8): sums 4 partials for 4 outputs
// via float4; smem tree over the 32 p-groups. Grid 416 x 256 = 106k threads.
__global__ __launch_bounds__(256) void red2_kernel(float* __restrict__ out)
{
    __shared__ float4 redq[32][8];
    const int t  = threadIdx.x;
    const int pg = t >> 3;              // 0..31
    const int ql = t & 7;               // 0..7
    const int Q  = blockIdx.x * 8 + ql; // global output quad (0..3327)
    const float* P = g_part + 4*Q;

    const int p0 = pg * 4;
    float4 v0 = *(const float4*)(P + (long)(p0 + 0)*PART);
    float4 v1 = *(const float4*)(P + (long)(p0 + 1)*PART);
    float4 v2 = *(const float4*)(P + (long)(p0 + 2)*PART);
    float4 v3 = *(const float4*)(P + (long)(p0 + 3)*PART);
    float4 a;
    a.x = (v0.x + v1.x) + (v2.x + v3.x);
    a.y = (v0.y + v1.y) + (v2.y + v3.y);
    a.z = (v0.z + v1.z) + (v2.z + v3.z);
    a.w = (v0.w + v1.w) + (v2.w + v3.w);
    redq[pg][ql] = a;
    __syncthreads();

    if (t < 8) {
        float4 s = redq[0][t];
#pragma unroll
        for (int qq = 1; qq < 32; qq++) {
            float4 v = redq[qq][t];
            s.x += v.x; s.y += v.y; s.z += v.z; s.w += v.w;
        }
        const int Qo = blockIdx.x * 8 + t;
        const float sv[4] = {s.x, s.y, s.z, s.w};
#pragma unroll
        for (int c4 = 0; c4 < 4; c4++) {
            int i = 4*Qo + c4;
            if (i < 12800) {
                int c = i >> 8, mm = i & 255;
                out[OFF_S + mm*INDIM + c] = sv[c4];
            } else if (i < 13056) {
                out[OFF_W + (i - 12800)] = sv[c4];
            } else {
                out[OFF_W + 256 + (i - 13056)] = sv[c4];
            }
        }
    }
}

extern "C" void kernel_launch(void* const* d_in, const int* in_sizes, int n_in,
                              void* d_out, int out_size)
{
    const float* U0  = (const float*)d_in[0];
    const float* U1  = (const float*)d_in[1];
    const float* U2  = (const float*)d_in[2];
    const float* S   = (const float*)d_in[3];
    const float* w   = (const float*)d_in[4];
    const float* tn  = (const float*)d_in[5];
    const float* obs = (const float*)d_in[6];
    const int*   idx = (const int*)d_in[7];
    float* out = (float*)d_out;

    const int smem_bytes = SMEM_FLOATS * (int)sizeof(float);
    cudaFuncSetAttribute(fwd_kernel, cudaFuncAttributeMaxDynamicSharedMemorySize, smem_bytes);

    fwd_kernel<<<NBLK, 512, smem_bytes>>>(U0, U1, U2, S, w, tn, obs, idx, out);
    red2_kernel<<<416, 256>>>(out);
}

// round 9
// speedup vs baseline: 1.5064x; 1.1111x over previous
#include <cuda_runtime.h>

// Problem constants
#define NB    512       // batch B
#define NMF   256       // M features
#define INDIM 50
#define SROW  51        // padded S row (conflict-free smem)
#define OFF_U 512
#define OFF_S 25088     // 512 + 512*48
#define OFF_W 37888     // OFF_S + 256*50
#define G     4         // batch elements per fwd block
#define NBLK  (NB/G)    // 128 fwd blocks
#define PART  13312     // per-block partial: 50*256 (grad_S, j-major) + 256 gc + 256 gs

__device__ float g_part[NBLK * PART];

__device__ __forceinline__ float warp_sum(float v) {
#pragma unroll
    for (int o = 16; o; o >>= 1) v += __shfl_down_sync(0xffffffffu, v, o);
    return v;
}
__device__ __forceinline__ float xor_sum(float v) {
#pragma unroll
    for (int o = 16; o; o >>= 1) v += __shfl_xor_sync(0xffffffffu, v, o);
    return v;
}
// Named barrier over one 256-thread half (ids 1 and 2)
#define BAR_HALF(h) asm volatile("bar.sync %0, 256;" :: "r"(1 + (h)) : "memory")

// smem floats: S[256*51] | inp[4*64] | red[4*64 + 16] | e4[4*256] | et/ex/gc/gs [4*256]
#define SMEM_FLOATS (NMF*SROW + 256 + 272 + 1024 + 4*1024)

// 512 threads: half = t>>8 handles g in {2*half, 2*half+1}; m = t & 255.
__global__ __launch_bounds__(512) void fwd_kernel(
    const float* __restrict__ U0, const float* __restrict__ U1,
    const float* __restrict__ U2, const float* __restrict__ S,
    const float* __restrict__ w,  const float* __restrict__ tn,
    const float* __restrict__ obs, const int* __restrict__ idx,
    float* __restrict__ out)
{
    extern __shared__ float sm[];
    float* Ssm   = sm;                    // 256*51 = 13056
    float* inp   = Ssm + NMF*SROW;        // 256
    float* red   = inp + 256;             // 272 ; [256..259] = lamA per g
    float* e4f   = red + 272;             // 1024: e packed [m][g]  (16B-aligned)
    float* et_sm = e4f + 1024;            // [4][256]
    float* ex_sm = et_sm + 1024;
    float* gc_sm = ex_sm + 1024;
    float* gs_sm = gc_sm + 1024;
    float4* e4   = (float4*)e4f;

    const int b0   = blockIdx.x * G;
    const int t    = threadIdx.x;
    const int lane = t & 31;
    const int wid  = t >> 5;             // 0..15
    const int m    = t & 255;
    const int half = t >> 8;             // 0 or 1
    const int w8   = wid & 7;
    const int g0   = half * 2;

    // Load S via float4, scatter into padded smem rows
    {
        const float4* S4 = (const float4*)S;
        for (int i = t; i < (NMF*INDIM)/4; i += 512) {
            float4 v = S4[i];
            int base = i * 4;
#pragma unroll
            for (int c = 0; c < 4; c++) {
                int id = base + c;
                int mm = id / INDIM;
                int jj = id - mm*INDIM;
                float vc = (c == 0) ? v.x : (c == 1) ? v.y : (c == 2) ? v.z : v.w;
                Ssm[mm*SROW + jj] = vc;
            }
        }
    }
    // Gather Uvec (4 b x 48 values)
    if (t < G*48) {
        int gg = t / 48, j = t - gg*48;
        int v = j >> 4, r = j & 15;
        int iv = idx[(b0 + gg)*3 + v];
        const float* Uv = (v == 0) ? U0 : (v == 1) ? U1 : U2;
        inp[gg*64 + 2 + j] = Uv[iv*16 + r];
    }
    __syncthreads();

    const float wc = w[m], ws = w[256 + m];
    const float s0 = Ssm[m*SROW + 0], s1 = Ssm[m*SROW + 1];

    float scaleT[2], obsg[2], beta[2], phiU[2];
#pragma unroll
    for (int gi = 0; gi < 2; gi++) {
        const int g = g0 + gi;
        scaleT[gi] = tn[b0 + g];
        obsg[gi]   = obs[b0 + g];
        const float* inpg = inp + g*64;
        float bt = 0.f;
        if (lane < 16) bt = inpg[2 + lane] * inpg[18 + lane] * inpg[34 + lane];
        beta[gi] = xor_sum(bt);
    }
    // phi constant part: one Ssm read feeds both g's
    {
        float a0 = 0.f, a1 = 0.f;
        const float* i0 = inp + g0*64;
        const float* i1 = inp + (g0 + 1)*64;
#pragma unroll
        for (int j = 2; j < INDIM; j++) {
            float sv = Ssm[m*SROW + j];
            a0 = fmaf(sv, i0[j], a0);
            a1 = fmaf(sv, i1[j], a1);
        }
        phiU[0] = a0; phiU[1] = a1;
    }

    // ---- RK4 stages (t = 0, 0.5, 0.5, 1 ; h = 1), state in registers ----
    float in0[2] = {0.f, 0.f};
    float in1[2] = {beta[0], beta[1]};
    float cpS[4][2], spS[4][2], kS[4][2], JS[4][2], xS[4][2], tS[4][2];
#pragma unroll
    for (int i = 0; i < 4; i++) {
        float fp[2], jp[2];
#pragma unroll
        for (int gi = 0; gi < 2; gi++) {
            xS[i][gi] = in1[gi]; tS[i][gi] = in0[gi];
            float phi = phiU[gi] + s0*in0[gi] + s1*in1[gi];
            float cp, sp;
            __sincosf(phi, &sp, &cp);
            cpS[i][gi] = cp; spS[i][gi] = sp;
            fp[gi] = xor_sum(cp*wc + sp*ws);
            jp[gi] = xor_sum((cp*ws - sp*wc) * s1);
        }
        if (lane == 0) {
#pragma unroll
            for (int gi = 0; gi < 2; gi++) {
                const int g = g0 + gi;
                red[i*64 + g*8 + w8]      = fp[gi];
                red[i*64 + 32 + g*8 + w8] = jp[gi];
            }
        }
        BAR_HALF(half);
#pragma unroll
        for (int gi = 0; gi < 2; gi++) {
            const int g = g0 + gi;
            const float4* rf = (const float4*)(red + i*64 + g*8);
            const float4* rj = (const float4*)(red + i*64 + 32 + g*8);
            float4 f0 = rf[0], f1 = rf[1], j0 = rj[0], j1 = rj[1];
            float F  = ((f0.x + f0.y) + (f0.z + f0.w)) + ((f1.x + f1.y) + (f1.z + f1.w));
            float JJ = ((j0.x + j0.y) + (j0.z + j0.w)) + ((j1.x + j1.y) + (j1.z + j1.w));
            float k = scaleT[gi] * F;
            kS[i][gi] = k; JS[i][gi] = scaleT[gi] * JJ;
            if (i < 2)      { in1[gi] = beta[gi] + 0.5f*k; in0[gi] = scaleT[gi]*0.5f; }
            else if (i == 2){ in1[gi] = beta[gi] + k;      in0[gi] = scaleT[gi]; }
        }
    }

    // Discrete-adjoint RK4 coefficients + pass 2 (registers only)
#pragma unroll
    for (int gi = 0; gi < 2; gi++) {
        const int g = g0 + gi;
        const float J1 = JS[0][gi], J2 = JS[1][gi], J3 = JS[2][gi], J4 = JS[3][gi];
        const float xT  = beta[gi] + (kS[0][gi] + 2.f*kS[1][gi] + 2.f*kS[2][gi] + kS[3][gi]) * (1.f/6.f);
        const float lam = (xT - obsg[gi]) * (1.f/512.f);
        const float a1 = J1;
        const float a2 = J2*(1.f + 0.5f*a1);
        const float a3 = J3*(1.f + 0.5f*a2);
        const float a4 = J4*(1.f + a3);
        const float A  = 1.f + (a1 + 2.f*a2 + 2.f*a3 + a4) * (1.f/6.f);
        const float ls = lam * scaleT[gi];
        float ch[4];
        ch[0] = ls * (1.f + J2 + 0.5f*J3*J2 + 0.25f*J4*J3*J2) * (1.f/6.f);
        ch[1] = ls * (2.f + J3 + 0.5f*J4*J3) * (1.f/6.f);
        ch[2] = ls * (2.f + J4) * (1.f/6.f);
        ch[3] = ls * (1.f/6.f);
        const float lamA = lam * A;
        if (m == 0) {
            out[b0 + g] = lamA;          // grad wrt beta (diagonal)
            red[256 + g] = lamA;
        }
        float e = 0.f, et = 0.f, ex = 0.f, gc = 0.f, gs = 0.f;
#pragma unroll
        for (int i = 0; i < 4; i++) {
            float d  = cpS[i][gi]*ws - spS[i][gi]*wc;
            float cd = ch[i] * d;
            e  += cd;
            et += cd * tS[i][gi];
            ex += cd * xS[i][gi];
            gc += ch[i] * cpS[i][gi];
            gs += ch[i] * spS[i][gi];
        }
        e4f  [m*4 + g]   = e;
        et_sm[g*256 + m] = et;
        ex_sm[g*256 + m] = ex;
        gc_sm[g*256 + m] = gc;
        gs_sm[g*256 + m] = gs;
    }
    __syncthreads();

    // ---- per-b Uvec gradient: task = j (48 tasks, 3/warp), all 4 g at once ----
    // grad_U[b0+g][j] = sum_m e[g][m] * S[m, 2+j] + lamA_g * prod_excl
#pragma unroll
    for (int q = 0; q < 3; q++) {
        const int j = wid*3 + q;
        float a0 = 0.f, a1 = 0.f, a2 = 0.f, a3 = 0.f;
#pragma unroll
        for (int k = 0; k < 8; k++) {
            int mm = lane + 32*k;
            float sv = Ssm[mm*SROW + 2 + j];
            float4 ev = e4[mm];
            a0 = fmaf(sv, ev.x, a0);
            a1 = fmaf(sv, ev.y, a1);
            a2 = fmaf(sv, ev.z, a2);
            a3 = fmaf(sv, ev.w, a3);
        }
        a0 = warp_sum(a0); a1 = warp_sum(a1); a2 = warp_sum(a2); a3 = warp_sum(a3);
        if (lane == 0) {
            const int v = j >> 4, r = j & 15;
            const float acc[4] = {a0, a1, a2, a3};
#pragma unroll
            for (int g = 0; g < 4; g++) {
                const float* inpg = inp + g*64;
                float u0 = inpg[2 + r], u1 = inpg[18 + r], u2 = inpg[34 + r];
                float pe = (v == 0) ? u1*u2 : (v == 1) ? u0*u2 : u0*u1;
                out[OFF_U + (b0 + g)*48 + j] = acc[g] + red[256 + g] * pe;
            }
        }
    }

    // ---- per-block partial grad_S (j-major) + grad_w ----
    {
        const long bp = (long)blockIdx.x * PART;
        const float4 ev = e4[m];
        const float eg0 = ev.x, eg1 = ev.y, eg2 = ev.z, eg3 = ev.w;
        if (half == 0) {
            g_part[bp + 0*256 + m] = et_sm[m] + et_sm[256+m] + et_sm[512+m] + et_sm[768+m];
            g_part[bp + 1*256 + m] = ex_sm[m] + ex_sm[256+m] + ex_sm[512+m] + ex_sm[768+m];
#pragma unroll
            for (int c = 2; c < 25; c++) {
                float s = eg0*inp[c] + eg1*inp[64+c] + eg2*inp[128+c] + eg3*inp[192+c];
                g_part[bp + c*256 + m] = s;
            }
            g_part[bp + 12800 + m] = gc_sm[m] + gc_sm[256+m] + gc_sm[512+m] + gc_sm[768+m];
        } else {
#pragma unroll
            for (int c = 25; c < 50; c++) {
                float s = eg0*inp[c] + eg1*inp[64+c] + eg2*inp[128+c] + eg3*inp[192+c];
                g_part[bp + c*256 + m] = s;
            }
            g_part[bp + 13056 + m] = gs_sm[m] + gs_sm[256+m] + gs_sm[512+m] + gs_sm[768+m];
        }
    }
}

// Stage 2: sum 128 per-block partials for each of 13312 outputs.
// thread = (p-group pg of 32, quad ql of 8): sums 4 partials for 4 outputs
// via float4; smem tree over the 32 p-groups. Grid 416 x 256 = 106k threads.
__global__ __launch_bounds__(256) void red2_kernel(float* __restrict__ out)
{
    __shared__ float4 redq[32][8];
    const int t  = threadIdx.x;
    const int pg = t >> 3;              // 0..31
    const int ql = t & 7;               // 0..7
    const int Q  = blockIdx.x * 8 + ql; // global output quad (0..3327)
    const float* P = g_part + 4*Q;

    const int p0 = pg * 4;
    float4 v0 = *(const float4*)(P + (long)(p0 + 0)*PART);
    float4 v1 = *(const float4*)(P + (long)(p0 + 1)*PART);
    float4 v2 = *(const float4*)(P + (long)(p0 + 2)*PART);
    float4 v3 = *(const float4*)(P + (long)(p0 + 3)*PART);
    float4 a;
    a.x = (v0.x + v1.x) + (v2.x + v3.x);
    a.y = (v0.y + v1.y) + (v2.y + v3.y);
    a.z = (v0.z + v1.z) + (v2.z + v3.z);
    a.w = (v0.w + v1.w) + (v2.w + v3.w);
    redq[pg][ql] = a;
    __syncthreads();

    if (t < 8) {
        float4 s = redq[0][t];
#pragma unroll
        for (int qq = 1; qq < 32; qq++) {
            float4 v = redq[qq][t];
            s.x += v.x; s.y += v.y; s.z += v.z; s.w += v.w;
        }
        const int Qo = blockIdx.x * 8 + t;
        const float sv[4] = {s.x, s.y, s.z, s.w};
#pragma unroll
        for (int c4 = 0; c4 < 4; c4++) {
            int i = 4*Qo + c4;
            if (i < 12800) {
                int c = i >> 8, mm = i & 255;
                out[OFF_S + mm*INDIM + c] = sv[c4];
            } else if (i < 13056) {
                out[OFF_W + (i - 12800)] = sv[c4];
            } else {
                out[OFF_W + 256 + (i - 13056)] = sv[c4];
            }
        }
    }
}

extern "C" void kernel_launch(void* const* d_in, const int* in_sizes, int n_in,
                              void* d_out, int out_size)
{
    const float* U0  = (const float*)d_in[0];
    const float* U1  = (const float*)d_in[1];
    const float* U2  = (const float*)d_in[2];
    const float* S   = (const float*)d_in[3];
    const float* w   = (const float*)d_in[4];
    const float* tn  = (const float*)d_in[5];
    const float* obs = (const float*)d_in[6];
    const int*   idx = (const int*)d_in[7];
    float* out = (float*)d_out;

    const int smem_bytes = SMEM_FLOATS * (int)sizeof(float);
    cudaFuncSetAttribute(fwd_kernel, cudaFuncAttributeMaxDynamicSharedMemorySize, smem_bytes);

    fwd_kernel<<<NBLK, 512, smem_bytes>>>(U0, U1, U2, S, w, tn, obs, idx, out);
    red2_kernel<<<416, 256>>>(out);
}